// round 15
// baseline (speedup 1.0000x reference)
#include <cuda_runtime.h>
#include <cuda_bf16.h>
#include <cstdint>

#define BATCH 8
#define C_DIM 512
#define N_DIM 4096
#define EPSV  1e-6f
#define SKM   4          // split-K for S = x x^T
#define SKG   2          // split-K for G = Aq Wk^T

// ---------------- scratch (device globals) -----------------------------------
__device__ __nv_bfloat16 g_xb [(size_t)BATCH * C_DIM * N_DIM];      // x bf16 [b][c][n]
__device__ __nv_bfloat16 g_wb[3ULL * C_DIM * C_DIM];                // Wq|Wk|Wv^T bf16
__device__ float         g_spart[(size_t)SKM * BATCH * C_DIM * C_DIM]; // S / G partials
__device__ __nv_bfloat16 g_sb[(size_t)BATCH * C_DIM * C_DIM];       // S bf16
__device__ __nv_bfloat16 g_ab[(size_t)BATCH * 2 * C_DIM * C_DIM];   // [Aq;Ak] bf16
__device__ float         g_nrm[(size_t)BATCH * 2 * C_DIM];          // |Q_i|^2, |K_i|^2
__device__ float         g_rsum[(size_t)BATCH * C_DIM];             // row L1 sums of M
__device__ float         g_m[(size_t)BATCH * C_DIM * C_DIM];        // M fp32 scratch
__device__ __nv_bfloat16 g_mb[(size_t)BATCH * C_DIM * C_DIM];       // M bf16 (unnorm rows)
__device__ __nv_bfloat16 g_mw[(size_t)BATCH * C_DIM * C_DIM];       // (M/row) @ Wv bf16

// ---------------- helpers -----------------------------------------------------
__device__ __forceinline__ uint32_t smem_u32(const void* p) {
    return (uint32_t)__cvta_generic_to_shared(p);
}
__device__ __forceinline__ void cpa16(uint32_t d, const void* s) {
    asm volatile("cp.async.cg.shared.global [%0], [%1], 16;\n" :: "r"(d), "l"(s));
}
__device__ __forceinline__ void ldsm4(uint32_t& r0, uint32_t& r1, uint32_t& r2, uint32_t& r3,
                                      uint32_t a) {
    asm volatile("ldmatrix.sync.aligned.m8n8.x4.shared.b16 {%0,%1,%2,%3}, [%4];\n"
                 : "=r"(r0), "=r"(r1), "=r"(r2), "=r"(r3) : "r"(a));
}
__device__ __forceinline__ void ldsm4t(uint32_t& r0, uint32_t& r1, uint32_t& r2, uint32_t& r3,
                                       uint32_t a) {
    asm volatile("ldmatrix.sync.aligned.m8n8.x4.trans.shared.b16 {%0,%1,%2,%3}, [%4];\n"
                 : "=r"(r0), "=r"(r1), "=r"(r2), "=r"(r3) : "r"(a));
}
__device__ __forceinline__ void mma16816(float* c, const uint32_t* a, uint32_t b0, uint32_t b1) {
    asm volatile("mma.sync.aligned.m16n8k16.row.col.f32.bf16.bf16.f32 "
                 "{%0,%1,%2,%3}, {%4,%5,%6,%7}, {%8,%9}, {%0,%1,%2,%3};\n"
                 : "+f"(c[0]), "+f"(c[1]), "+f"(c[2]), "+f"(c[3])
                 : "r"(a[0]), "r"(a[1]), "r"(a[2]), "r"(a[3]), "r"(b0), "r"(b1));
}

// ---------------- bf16 GEMM: 128x128 CTA, 64x32 warp tile, 2-stage ------------
// A always NT ([m][k], k contiguous).  BNN=0: B [n][k] NT.  BNN=1: B [k][n] NN.
// EPI 0: fp32.  EPI 1: C = X + gamma*acc (fp32).  EPI 3: bf16.
// EPI 5: bf16, acc scaled by 1/(rowsum[m]+eps) (rowsum passed via X).
// SYMM 1: early-exit tiles strictly below the diagonal.
#define BM 128
#define BN 128
#define BK 64
#define STG_BYTES 32768

template <int EPI, int SYMM = 0, int BNN = 0>
__global__ __launch_bounds__(256, 2) void gemm_nt(
    const __nv_bfloat16* __restrict__ A, const __nv_bfloat16* __restrict__ B,
    void* __restrict__ Cv, int Nld, int K, int lda, int ldb,
    long long strA, long long strB, long long strC, int SK, long long kcStr,
    const float* __restrict__ X, const float* __restrict__ gamma)
{
    extern __shared__ char smraw[];
    int m0 = blockIdx.y * BM, n0 = blockIdx.x * BN;
    if (SYMM && m0 > n0) return;

    int bz = blockIdx.z;
    int b = bz / SK, kc = bz - b * SK;
    A += (size_t)b * strA + (size_t)kc * K;
    B += (size_t)b * strB + (size_t)(BNN ? 0 : kc * K);

    int tid = threadIdx.x;
    int lane = tid & 31, w = tid >> 5;
    int wm = (w & 1) * 64;
    int wn = (w >> 1) * 32;
    int r = lane >> 2, q = lane & 3;

    uint32_t sbase = smem_u32(smraw);

    float acc[4][4][4];
#pragma unroll
    for (int mi = 0; mi < 4; mi++)
#pragma unroll
        for (int ni = 0; ni < 4; ni++)
#pragma unroll
            for (int t = 0; t < 4; t++) acc[mi][ni][t] = 0.f;

    int lr = tid >> 3, lc = tid & 7;
    int rowb = tid >> 2, lc4 = tid & 3;   // BNN B-tile mapping

    auto issue = [&](int kt, int s) {
        uint32_t sA = sbase + s * STG_BYTES;
        uint32_t sB = sA + 16384;
        const __nv_bfloat16* Ag = A + (size_t)kt * BK;
#pragma unroll
        for (int p = 0; p < 4; p++) {
            int row = lr + p * 32;
            cpa16(sA + row * 128 + ((lc ^ (row & 7)) << 4),
                  Ag + (size_t)(m0 + row) * lda + lc * 8);
        }
        if (BNN) {
            const __nv_bfloat16* Bg = B + (size_t)kt * BK * ldb;
#pragma unroll
            for (int p = 0; p < 4; p++) {
                int ch = lc4 + p * 4;
                cpa16(sB + rowb * 256 + ((ch ^ (rowb & 7)) << 4),
                      Bg + (size_t)rowb * ldb + n0 + ch * 8);
            }
        } else {
            const __nv_bfloat16* Bg = B + (size_t)kt * BK;
#pragma unroll
            for (int p = 0; p < 4; p++) {
                int row = lr + p * 32;
                cpa16(sB + row * 128 + ((lc ^ (row & 7)) << 4),
                      Bg + (size_t)(n0 + row) * ldb + lc * 8);
            }
        }
        asm volatile("cp.async.commit_group;\n");
    };

    int nk = K / BK;
    issue(0, 0);

    for (int kt = 0; kt < nk; kt++) {
        int cur = kt & 1;
        if (kt + 1 < nk) {
            issue(kt + 1, cur ^ 1);
            asm volatile("cp.async.wait_group 1;\n");
        } else {
            asm volatile("cp.async.wait_group 0;\n");
        }
        __syncthreads();

        uint32_t sA = sbase + cur * STG_BYTES;
        uint32_t sB = sA + 16384;
#pragma unroll
        for (int ks = 0; ks < BK / 16; ks++) {
            uint32_t ra[4][4], rb[2][4];
            int kca = ks * 2 + (lane >> 4);
#pragma unroll
            for (int mi = 0; mi < 4; mi++) {
                int row = wm + mi * 16 + (lane & 15);
                ldsm4(ra[mi][0], ra[mi][1], ra[mi][2], ra[mi][3],
                      sA + row * 128 + ((kca ^ (row & 7)) << 4));
            }
            if (BNN) {
                int krow = ks * 16 + ((lane >> 3) & 1) * 8 + (lane & 7);
#pragma unroll
                for (int nj = 0; nj < 2; nj++) {
                    int ch = ((wn + nj * 16) >> 3) + (lane >> 4);
                    ldsm4t(rb[nj][0], rb[nj][1], rb[nj][2], rb[nj][3],
                           sB + krow * 256 + ((ch ^ (krow & 7)) << 4));
                }
            } else {
                int kcb = ks * 2 + ((lane >> 3) & 1);
                int rbo = (lane & 7) + ((lane >> 4) << 3);
#pragma unroll
                for (int nj = 0; nj < 2; nj++) {
                    int row = wn + nj * 16 + rbo;
                    ldsm4(rb[nj][0], rb[nj][1], rb[nj][2], rb[nj][3],
                          sB + row * 128 + ((kcb ^ (row & 7)) << 4));
                }
            }
#pragma unroll
            for (int mi = 0; mi < 4; mi++)
#pragma unroll
                for (int nj = 0; nj < 2; nj++) {
                    mma16816(acc[mi][2 * nj],     ra[mi], rb[nj][0], rb[nj][1]);
                    mma16816(acc[mi][2 * nj + 1], ra[mi], rb[nj][2], rb[nj][3]);
                }
        }
        __syncthreads();
    }

    if (EPI == 3 || EPI == 5) {
        __nv_bfloat16* C = (__nv_bfloat16*)Cv + (size_t)b * strC;
#pragma unroll
        for (int mi = 0; mi < 4; mi++) {
            int row = m0 + wm + mi * 16 + r;
            float i0 = 1.f, i1 = 1.f;
            if (EPI == 5) {
                const float* rsv = X + (size_t)b * C_DIM;
                i0 = 1.f / (rsv[row] + EPSV);
                i1 = 1.f / (rsv[row + 8] + EPSV);
            }
#pragma unroll
            for (int ni = 0; ni < 4; ni++) {
                int col = n0 + wn + ni * 8 + 2 * q;
                *(__nv_bfloat162*)&C[(size_t)row * Nld + col] =
                    __floats2bfloat162_rn(acc[mi][ni][0] * i0, acc[mi][ni][1] * i0);
                *(__nv_bfloat162*)&C[(size_t)(row + 8) * Nld + col] =
                    __floats2bfloat162_rn(acc[mi][ni][2] * i1, acc[mi][ni][3] * i1);
            }
        }
    } else {
        float* C = (float*)Cv + (size_t)b * strC + (size_t)kc * kcStr;
        float g = 0.f;
        const float* xb = nullptr;
        if (EPI == 1) { g = gamma[0]; xb = X + (size_t)b * strC; }
#pragma unroll
        for (int mi = 0; mi < 4; mi++)
#pragma unroll
            for (int ni = 0; ni < 4; ni++) {
                int row = m0 + wm + mi * 16 + r;
                int col = n0 + wn + ni * 8 + 2 * q;
                size_t o0 = (size_t)row * Nld + col;
                size_t o1 = (size_t)(row + 8) * Nld + col;
                if (EPI == 0) {
                    *(float2*)&C[o0] = make_float2(acc[mi][ni][0], acc[mi][ni][1]);
                    *(float2*)&C[o1] = make_float2(acc[mi][ni][2], acc[mi][ni][3]);
                } else {
                    float2 x0 = *(const float2*)&xb[o0];
                    float2 x1 = *(const float2*)&xb[o1];
                    *(float2*)&C[o0] = make_float2(x0.x + g * acc[mi][ni][0],
                                                   x0.y + g * acc[mi][ni][1]);
                    *(float2*)&C[o1] = make_float2(x1.x + g * acc[mi][ni][2],
                                                   x1.y + g * acc[mi][ni][3]);
                }
            }
    }
}

// ---------------- x -> bf16 streaming convert ---------------------------------
__global__ __launch_bounds__(256) void cvt_x(const float* __restrict__ src) {
    const size_t nv = (size_t)BATCH * C_DIM * N_DIM / 4;   // float4 count
    size_t i = (size_t)blockIdx.x * 256 + threadIdx.x;
    const float4* s4 = (const float4*)src;
    __nv_bfloat162* d = (__nv_bfloat162*)g_xb;
    for (; i < nv; i += (size_t)gridDim.x * 256) {
        float4 v = s4[i];
        d[2 * i]     = __floats2bfloat162_rn(v.x, v.y);
        d[2 * i + 1] = __floats2bfloat162_rn(v.z, v.w);
    }
}

// weights -> bf16: [Wq;Wk] stacked, Wv transposed; zero rsum
__global__ void cvt_w(const float* __restrict__ wq, const float* __restrict__ wk,
                      const float* __restrict__ wv) {
    int i = blockIdx.x * blockDim.x + threadIdx.x;
    if (i < C_DIM * C_DIM) {
        g_wb[i]                 = __float2bfloat16(wq[i]);
        g_wb[i + C_DIM * C_DIM] = __float2bfloat16(wk[i]);
        int o = i >> 9, c = i & (C_DIM - 1);
        g_wb[2 * C_DIM * C_DIM + c * C_DIM + o] = __float2bfloat16(wv[i]);  // Wv^T
    }
    if (i < BATCH * C_DIM) g_rsum[i] = 0.f;
}

// ---------------- sum S partials (upper-tri) -> bf16, mirror strict-upper -----
__global__ void sum_s_t() {
    int b = blockIdx.z;
    int d0 = blockIdx.x * 32, c0 = blockIdx.y * 32;
    if ((c0 >> 7) > (d0 >> 7)) return;
    bool mirror = (c0 >> 7) < (d0 >> 7);

    const size_t cc = (size_t)C_DIM * C_DIM;
    const size_t tot = (size_t)BATCH * cc;
    const float* P = g_spart + (size_t)b * cc;
    __nv_bfloat16* Sb = g_sb + (size_t)b * cc;

    __shared__ __nv_bfloat16 tile[32][33];
#pragma unroll
    for (int i = 0; i < 32; i += 8) {
        size_t idx = (size_t)(c0 + threadIdx.y + i) * C_DIM + d0 + threadIdx.x;
        __nv_bfloat16 v = __float2bfloat16(P[idx] + P[idx + tot] +
                                           P[idx + 2 * tot] + P[idx + 3 * tot]);
        Sb[idx] = v;
        tile[threadIdx.y + i][threadIdx.x] = v;
    }
    if (mirror) {
        __syncthreads();
#pragma unroll
        for (int i = 0; i < 32; i += 8)
            Sb[(size_t)(d0 + threadIdx.y + i) * C_DIM + c0 + threadIdx.x] =
                tile[threadIdx.x][threadIdx.y + i];
    }
}

// ---------------- row norms: nrm[b][r] = A[b][r] . W[r] -----------------------
__global__ __launch_bounds__(256) void norm_dots() {
    int b = blockIdx.y;
    int row = blockIdx.x * 8 + (threadIdx.x >> 5);
    int lane = threadIdx.x & 31;
    const __nv_bfloat162* a =
        (const __nv_bfloat162*)(g_ab + ((size_t)b * 2 * C_DIM + row) * C_DIM);
    const __nv_bfloat162* wr = (const __nv_bfloat162*)(g_wb + (size_t)row * C_DIM);
    float s = 0.f;
#pragma unroll
    for (int i = lane; i < C_DIM / 2; i += 32) {
        __nv_bfloat162 av = a[i], wv2 = wr[i];
        s += __bfloat162float(av.x) * __bfloat162float(wv2.x)
           + __bfloat162float(av.y) * __bfloat162float(wv2.y);
    }
#pragma unroll
    for (int o = 16; o; o >>= 1) s += __shfl_xor_sync(0xffffffffu, s, o);
    if (lane == 0) g_nrm[(size_t)b * 2 * C_DIM + row] = s;
}

// ---------------- col ops: sum G partials, norm-scale, softmax -> bf16 M ------
__global__ __launch_bounds__(512) void col_ops() {
    int b = blockIdx.y;
    int tx = threadIdx.x, ty = threadIdx.y;
    int d = blockIdx.x * 32 + tx;
    const size_t cc = (size_t)C_DIM * C_DIM;
    float* Mo = g_m + (size_t)b * cc;
    __nv_bfloat16* Mb = g_mb + (size_t)b * cc;
    const float* P = g_spart + (size_t)b * cc;
    const size_t ks2 = (size_t)BATCH * cc;
    const float* nb = g_nrm + (size_t)b * 2 * C_DIM;

    __shared__ float inq_s[C_DIM];
    int li = ty * 32 + tx;
    inq_s[li] = rsqrtf(nb[li]);
    float ink = rsqrtf(nb[C_DIM + d]);
    __syncthreads();

    float mmax = -1e30f, mmin = 1e30f;
    for (int c = ty; c < C_DIM; c += 16) {
        size_t o = (size_t)c * C_DIM + d;
        float m = (P[o] + P[o + ks2]) * inq_s[c] * ink;
        Mo[o] = m;
        mmax = fmaxf(mmax, m);
        mmin = fminf(mmin, m);
    }
    __shared__ float s1[16][33], s2[16][33];
    s1[ty][tx] = mmax; s2[ty][tx] = mmin;
    __syncthreads();
#pragma unroll
    for (int h = 8; h; h >>= 1) {
        if (ty < h) {
            s1[ty][tx] = fmaxf(s1[ty][tx], s1[ty + h][tx]);
            s2[ty][tx] = fminf(s2[ty][tx], s2[ty + h][tx]);
        }
        __syncthreads();
    }
    mmax = s1[0][tx]; mmin = s2[0][tx];
    __syncthreads();

    float inv = 4.0f / (1.0f - mmin + EPSV);
    float es = 0.f;
    for (int c = ty; c < C_DIM; c += 16) {
        size_t o = (size_t)c * C_DIM + d;
        float e = __expf((Mo[o] - mmax) * inv);
        Mo[o] = e;
        es += e;
    }
    s1[ty][tx] = es;
    __syncthreads();
#pragma unroll
    for (int h = 8; h; h >>= 1) {
        if (ty < h) s1[ty][tx] += s1[ty + h][tx];
        __syncthreads();
    }
    float rs = 1.0f / s1[0][tx];
    float* rsum = g_rsum + (size_t)b * C_DIM;
    for (int c = ty; c < C_DIM; c += 16) {
        size_t o = (size_t)c * C_DIM + d;
        float v = Mo[o] * rs;
        Mb[o] = __float2bfloat16(v);
        float t = v;
#pragma unroll
        for (int off = 16; off; off >>= 1) t += __shfl_xor_sync(0xffffffffu, t, off);
        if (tx == 0) atomicAdd(&rsum[c], t);
    }
}

// ---------------- launch ------------------------------------------------------
extern "C" void kernel_launch(void* const* d_in, const int* in_sizes, int n_in,
                              void* d_out, int out_size) {
    const float* x  = (const float*)d_in[0];
    const float* wq = (const float*)d_in[1];
    const float* wk = (const float*)d_in[2];
    const float* wv = (const float*)d_in[3];
    const float* gamma = (const float*)d_in[4];
    float* out = (float*)d_out;

    void *p_xb, *p_wb, *p_spart, *p_sb, *p_ab, *p_rsum, *p_mb, *p_mw;
    cudaGetSymbolAddress(&p_xb,  g_xb);
    cudaGetSymbolAddress(&p_wb,  g_wb);
    cudaGetSymbolAddress(&p_spart, g_spart);
    cudaGetSymbolAddress(&p_sb,  g_sb);
    cudaGetSymbolAddress(&p_ab,  g_ab);
    cudaGetSymbolAddress(&p_rsum, g_rsum);
    cudaGetSymbolAddress(&p_mb,  g_mb);
    cudaGetSymbolAddress(&p_mw,  g_mw);

    cudaFuncSetAttribute((const void*)gemm_nt<0, 1>, cudaFuncAttributeMaxDynamicSharedMemorySize, 2 * STG_BYTES);
    cudaFuncSetAttribute(gemm_nt<0>, cudaFuncAttributeMaxDynamicSharedMemorySize, 2 * STG_BYTES);
    cudaFuncSetAttribute(gemm_nt<3>, cudaFuncAttributeMaxDynamicSharedMemorySize, 2 * STG_BYTES);
    cudaFuncSetAttribute(gemm_nt<5>, cudaFuncAttributeMaxDynamicSharedMemorySize, 2 * STG_BYTES);
    cudaFuncSetAttribute((const void*)gemm_nt<1, 0, 1>, cudaFuncAttributeMaxDynamicSharedMemorySize, 2 * STG_BYTES);

    const long long CN = (long long)C_DIM * N_DIM;
    const long long CC = (long long)C_DIM * C_DIM;

    // 1) x -> bf16 (streaming)
    cvt_x<<<4096, 256>>>(x);
    // 2) weights -> bf16 ([Wq;Wk] | Wv^T), zero rsum
    cvt_w<<<(C_DIM * C_DIM + 255) / 256, 256>>>(wq, wk, wv);
    // 3) S partials = x @ x^T (upper-tri tiles only), split-K=4
    gemm_nt<0, 1><<<dim3(C_DIM / BN, C_DIM / BM, BATCH * SKM), 256, 2 * STG_BYTES>>>(
        (const __nv_bfloat16*)p_xb, (const __nv_bfloat16*)p_xb, p_spart,
        C_DIM, N_DIM / SKM, N_DIM, N_DIM,
        CN, CN, CC, SKM, (long long)BATCH * CC, nullptr, nullptr);
    // 4) S = sum partials -> bf16, mirror
    sum_s_t<<<dim3(16, 16, BATCH), dim3(32, 8)>>>();
    // 5) [Aq;Ak] = [Wq;Wk] @ S : M=1024, N=512, K=512 -> bf16
    gemm_nt<3><<<dim3(C_DIM / BN, 1024 / BM, BATCH), 256, 2 * STG_BYTES>>>(
        (const __nv_bfloat16*)p_wb, (const __nv_bfloat16*)p_sb, p_ab,
        C_DIM, C_DIM, C_DIM, C_DIM,
        0LL, CC, 2 * CC, 1, 0LL, nullptr, nullptr);
    // 6) norms
    norm_dots<<<dim3(2 * C_DIM / 8, BATCH), 256>>>();
    // 7) G partials = Aq @ Wk^T, split-K=2 (per-chunk K=256) -> g_spart
    gemm_nt<0><<<dim3(C_DIM / BN, C_DIM / BM, BATCH * SKG), 256, 2 * STG_BYTES>>>(
        (const __nv_bfloat16*)p_ab, (const __nv_bfloat16*)p_wb + CC, p_spart,
        C_DIM, C_DIM / SKG, C_DIM, C_DIM,
        2 * CC, 0LL, CC, SKG, (long long)BATCH * CC, nullptr, nullptr);
    // 8) col softmax (sums 2 G partials) -> bf16 M + row sums
    col_ops<<<dim3(C_DIM / 32, BATCH), dim3(32, 16)>>>();
    // 9) MW = (M/rowsum) @ Wv -> bf16 (EPI=5, rowsum via X)
    gemm_nt<5><<<dim3(C_DIM / BN, C_DIM / BM, BATCH), 256, 2 * STG_BYTES>>>(
        (const __nv_bfloat16*)p_mb, (const __nv_bfloat16*)p_wb + 2 * CC, p_mw,
        C_DIM, C_DIM, C_DIM, C_DIM,
        CC, 0LL, CC, 1, 0LL, (const float*)p_rsum, nullptr);
    // 10) out = x + gamma * (MW @ x) : NN B (x in [c][n] layout)
    gemm_nt<1, 0, 1><<<dim3(N_DIM / BN, C_DIM / BM, BATCH), 256, 2 * STG_BYTES>>>(
        (const __nv_bfloat16*)p_mw, (const __nv_bfloat16*)p_xb, out,
        N_DIM, C_DIM, C_DIM, N_DIM,
        CC, CN, CN, 1, 0LL, x, gamma);
}

// round 17
// speedup vs baseline: 1.0741x; 1.0741x over previous
#include <cuda_runtime.h>
#include <cuda_bf16.h>
#include <cstdint>

#define BATCH 8
#define C_DIM 512
#define N_DIM 4096
#define EPSV  1e-6f
#define SKM   4          // split-K for S = x x^T

// ---------------- scratch (device globals) -----------------------------------
__device__ __nv_bfloat16 g_xb [(size_t)BATCH * C_DIM * N_DIM];      // x bf16 [b][c][n]
__device__ __nv_bfloat16 g_wb[3ULL * C_DIM * C_DIM];                // Wq|Wk|Wv^T bf16
__device__ float         g_spart[(size_t)SKM * BATCH * C_DIM * C_DIM]; // S partials
__device__ __nv_bfloat16 g_sb[(size_t)BATCH * C_DIM * C_DIM];       // S bf16
__device__ __nv_bfloat16 g_ab[(size_t)BATCH * 2 * C_DIM * C_DIM];   // [Aq;Ak] bf16
__device__ float         g_nrm[(size_t)BATCH * 2 * C_DIM];          // |Q_i|^2, |K_i|^2
__device__ float         g_rsum[(size_t)BATCH * C_DIM];             // row L1 sums of M
__device__ float         g_m[(size_t)BATCH * C_DIM * C_DIM];        // G fp32
__device__ __nv_bfloat16 g_mb[(size_t)BATCH * C_DIM * C_DIM];       // M bf16 (unnorm rows)
__device__ __nv_bfloat16 g_mw[(size_t)BATCH * C_DIM * C_DIM];       // (M/row) @ Wv bf16

// ---------------- helpers -----------------------------------------------------
__device__ __forceinline__ uint32_t smem_u32(const void* p) {
    return (uint32_t)__cvta_generic_to_shared(p);
}
__device__ __forceinline__ void cpa16(uint32_t d, const void* s) {
    asm volatile("cp.async.cg.shared.global [%0], [%1], 16;\n" :: "r"(d), "l"(s));
}
__device__ __forceinline__ void ldsm4(uint32_t& r0, uint32_t& r1, uint32_t& r2, uint32_t& r3,
                                      uint32_t a) {
    asm volatile("ldmatrix.sync.aligned.m8n8.x4.shared.b16 {%0,%1,%2,%3}, [%4];\n"
                 : "=r"(r0), "=r"(r1), "=r"(r2), "=r"(r3) : "r"(a));
}
__device__ __forceinline__ void ldsm4t(uint32_t& r0, uint32_t& r1, uint32_t& r2, uint32_t& r3,
                                       uint32_t a) {
    asm volatile("ldmatrix.sync.aligned.m8n8.x4.trans.shared.b16 {%0,%1,%2,%3}, [%4];\n"
                 : "=r"(r0), "=r"(r1), "=r"(r2), "=r"(r3) : "r"(a));
}
__device__ __forceinline__ void mma16816(float* c, const uint32_t* a, uint32_t b0, uint32_t b1) {
    asm volatile("mma.sync.aligned.m16n8k16.row.col.f32.bf16.bf16.f32 "
                 "{%0,%1,%2,%3}, {%4,%5,%6,%7}, {%8,%9}, {%0,%1,%2,%3};\n"
                 : "+f"(c[0]), "+f"(c[1]), "+f"(c[2]), "+f"(c[3])
                 : "r"(a[0]), "r"(a[1]), "r"(a[2]), "r"(a[3]), "r"(b0), "r"(b1));
}

// ---------------- bf16 GEMM: 128x128 CTA, 64x32 warp tile, 2-stage ------------
// A always NT ([m][k], k contiguous).  BNN=0: B [n][k] NT.  BNN=1: B [k][n] NN.
// EPI 0: fp32.  EPI 1: C = X + gamma*acc (fp32).  EPI 3: bf16.
// EPI 5: bf16, acc scaled by 1/(rowsum[m]+eps) (rowsum passed via X).
// SYMM 1: early-exit tiles strictly below the diagonal.
#define BM 128
#define BN 128
#define BK 64
#define STG_BYTES 32768

template <int EPI, int SYMM = 0, int BNN = 0>
__global__ __launch_bounds__(256, 2) void gemm_nt(
    const __nv_bfloat16* __restrict__ A, const __nv_bfloat16* __restrict__ B,
    void* __restrict__ Cv, int Nld, int K, int lda, int ldb,
    long long strA, long long strB, long long strC, int SK, long long kcStr,
    const float* __restrict__ X, const float* __restrict__ gamma)
{
    extern __shared__ char smraw[];
    int m0 = blockIdx.y * BM, n0 = blockIdx.x * BN;
    if (SYMM && m0 > n0) return;

    int bz = blockIdx.z;
    int b = bz / SK, kc = bz - b * SK;
    A += (size_t)b * strA + (size_t)kc * K;
    B += (size_t)b * strB + (size_t)(BNN ? 0 : kc * K);

    int tid = threadIdx.x;
    int lane = tid & 31, w = tid >> 5;
    int wm = (w & 1) * 64;
    int wn = (w >> 1) * 32;
    int r = lane >> 2, q = lane & 3;

    uint32_t sbase = smem_u32(smraw);

    float acc[4][4][4];
#pragma unroll
    for (int mi = 0; mi < 4; mi++)
#pragma unroll
        for (int ni = 0; ni < 4; ni++)
#pragma unroll
            for (int t = 0; t < 4; t++) acc[mi][ni][t] = 0.f;

    int lr = tid >> 3, lc = tid & 7;
    int rowb = tid >> 2, lc4 = tid & 3;   // BNN B-tile mapping

    auto issue = [&](int kt, int s) {
        uint32_t sA = sbase + s * STG_BYTES;
        uint32_t sB = sA + 16384;
        const __nv_bfloat16* Ag = A + (size_t)kt * BK;
#pragma unroll
        for (int p = 0; p < 4; p++) {
            int row = lr + p * 32;
            cpa16(sA + row * 128 + ((lc ^ (row & 7)) << 4),
                  Ag + (size_t)(m0 + row) * lda + lc * 8);
        }
        if (BNN) {
            const __nv_bfloat16* Bg = B + (size_t)kt * BK * ldb;
#pragma unroll
            for (int p = 0; p < 4; p++) {
                int ch = lc4 + p * 4;
                cpa16(sB + rowb * 256 + ((ch ^ (rowb & 7)) << 4),
                      Bg + (size_t)rowb * ldb + n0 + ch * 8);
            }
        } else {
            const __nv_bfloat16* Bg = B + (size_t)kt * BK;
#pragma unroll
            for (int p = 0; p < 4; p++) {
                int row = lr + p * 32;
                cpa16(sB + row * 128 + ((lc ^ (row & 7)) << 4),
                      Bg + (size_t)(n0 + row) * ldb + lc * 8);
            }
        }
        asm volatile("cp.async.commit_group;\n");
    };

    int nk = K / BK;
    issue(0, 0);

    for (int kt = 0; kt < nk; kt++) {
        int cur = kt & 1;
        if (kt + 1 < nk) {
            issue(kt + 1, cur ^ 1);
            asm volatile("cp.async.wait_group 1;\n");
        } else {
            asm volatile("cp.async.wait_group 0;\n");
        }
        __syncthreads();

        uint32_t sA = sbase + cur * STG_BYTES;
        uint32_t sB = sA + 16384;
#pragma unroll
        for (int ks = 0; ks < BK / 16; ks++) {
            uint32_t ra[4][4], rb[2][4];
            int kca = ks * 2 + (lane >> 4);
#pragma unroll
            for (int mi = 0; mi < 4; mi++) {
                int row = wm + mi * 16 + (lane & 15);
                ldsm4(ra[mi][0], ra[mi][1], ra[mi][2], ra[mi][3],
                      sA + row * 128 + ((kca ^ (row & 7)) << 4));
            }
            if (BNN) {
                int krow = ks * 16 + ((lane >> 3) & 1) * 8 + (lane & 7);
#pragma unroll
                for (int nj = 0; nj < 2; nj++) {
                    int ch = ((wn + nj * 16) >> 3) + (lane >> 4);
                    ldsm4t(rb[nj][0], rb[nj][1], rb[nj][2], rb[nj][3],
                           sB + krow * 256 + ((ch ^ (krow & 7)) << 4));
                }
            } else {
                int kcb = ks * 2 + ((lane >> 3) & 1);
                int rbo = (lane & 7) + ((lane >> 4) << 3);
#pragma unroll
                for (int nj = 0; nj < 2; nj++) {
                    int row = wn + nj * 16 + rbo;
                    ldsm4(rb[nj][0], rb[nj][1], rb[nj][2], rb[nj][3],
                          sB + row * 128 + ((kcb ^ (row & 7)) << 4));
                }
            }
#pragma unroll
            for (int mi = 0; mi < 4; mi++)
#pragma unroll
                for (int nj = 0; nj < 2; nj++) {
                    mma16816(acc[mi][2 * nj],     ra[mi], rb[nj][0], rb[nj][1]);
                    mma16816(acc[mi][2 * nj + 1], ra[mi], rb[nj][2], rb[nj][3]);
                }
        }
        __syncthreads();
    }

    if (EPI == 3 || EPI == 5) {
        __nv_bfloat16* C = (__nv_bfloat16*)Cv + (size_t)b * strC;
#pragma unroll
        for (int mi = 0; mi < 4; mi++) {
            int row = m0 + wm + mi * 16 + r;
            float i0 = 1.f, i1 = 1.f;
            if (EPI == 5) {
                const float* rsv = X + (size_t)b * C_DIM;
                i0 = 1.f / (rsv[row] + EPSV);
                i1 = 1.f / (rsv[row + 8] + EPSV);
            }
#pragma unroll
            for (int ni = 0; ni < 4; ni++) {
                int col = n0 + wn + ni * 8 + 2 * q;
                *(__nv_bfloat162*)&C[(size_t)row * Nld + col] =
                    __floats2bfloat162_rn(acc[mi][ni][0] * i0, acc[mi][ni][1] * i0);
                *(__nv_bfloat162*)&C[(size_t)(row + 8) * Nld + col] =
                    __floats2bfloat162_rn(acc[mi][ni][2] * i1, acc[mi][ni][3] * i1);
            }
        }
    } else {
        float* C = (float*)Cv + (size_t)b * strC + (size_t)kc * kcStr;
        float g = 0.f;
        const float* xb = nullptr;
        if (EPI == 1) { g = gamma[0]; xb = X + (size_t)b * strC; }
#pragma unroll
        for (int mi = 0; mi < 4; mi++)
#pragma unroll
            for (int ni = 0; ni < 4; ni++) {
                int row = m0 + wm + mi * 16 + r;
                int col = n0 + wn + ni * 8 + 2 * q;
                size_t o0 = (size_t)row * Nld + col;
                size_t o1 = (size_t)(row + 8) * Nld + col;
                if (EPI == 0) {
                    *(float2*)&C[o0] = make_float2(acc[mi][ni][0], acc[mi][ni][1]);
                    *(float2*)&C[o1] = make_float2(acc[mi][ni][2], acc[mi][ni][3]);
                } else {
                    float2 x0 = *(const float2*)&xb[o0];
                    float2 x1 = *(const float2*)&xb[o1];
                    *(float2*)&C[o0] = make_float2(x0.x + g * acc[mi][ni][0],
                                                   x0.y + g * acc[mi][ni][1]);
                    *(float2*)&C[o1] = make_float2(x1.x + g * acc[mi][ni][2],
                                                   x1.y + g * acc[mi][ni][3]);
                }
            }
    }
}

// ---------------- x -> bf16 streaming convert ---------------------------------
__global__ __launch_bounds__(256) void cvt_x(const float* __restrict__ src) {
    const size_t nv = (size_t)BATCH * C_DIM * N_DIM / 4;   // float4 count
    size_t i = (size_t)blockIdx.x * 256 + threadIdx.x;
    const float4* s4 = (const float4*)src;
    __nv_bfloat162* d = (__nv_bfloat162*)g_xb;
    for (; i < nv; i += (size_t)gridDim.x * 256) {
        float4 v = s4[i];
        d[2 * i]     = __floats2bfloat162_rn(v.x, v.y);
        d[2 * i + 1] = __floats2bfloat162_rn(v.z, v.w);
    }
}

// weights -> bf16: [Wq;Wk] stacked, Wv transposed; zero rsum
__global__ void cvt_w(const float* __restrict__ wq, const float* __restrict__ wk,
                      const float* __restrict__ wv) {
    int i = blockIdx.x * blockDim.x + threadIdx.x;
    if (i < C_DIM * C_DIM) {
        g_wb[i]                 = __float2bfloat16(wq[i]);
        g_wb[i + C_DIM * C_DIM] = __float2bfloat16(wk[i]);
        int o = i >> 9, c = i & (C_DIM - 1);
        g_wb[2 * C_DIM * C_DIM + c * C_DIM + o] = __float2bfloat16(wv[i]);  // Wv^T
    }
    if (i < BATCH * C_DIM) g_rsum[i] = 0.f;
}

// ---------------- sum S partials (upper-tri) -> bf16, mirror strict-upper -----
__global__ void sum_s_t() {
    int b = blockIdx.z;
    int d0 = blockIdx.x * 32, c0 = blockIdx.y * 32;
    if ((c0 >> 7) > (d0 >> 7)) return;
    bool mirror = (c0 >> 7) < (d0 >> 7);

    const size_t cc = (size_t)C_DIM * C_DIM;
    const size_t tot = (size_t)BATCH * cc;
    const float* P = g_spart + (size_t)b * cc;
    __nv_bfloat16* Sb = g_sb + (size_t)b * cc;

    __shared__ __nv_bfloat16 tile[32][33];
#pragma unroll
    for (int i = 0; i < 32; i += 8) {
        size_t idx = (size_t)(c0 + threadIdx.y + i) * C_DIM + d0 + threadIdx.x;
        __nv_bfloat16 v = __float2bfloat16(P[idx] + P[idx + tot] +
                                           P[idx + 2 * tot] + P[idx + 3 * tot]);
        Sb[idx] = v;
        tile[threadIdx.y + i][threadIdx.x] = v;
    }
    if (mirror) {
        __syncthreads();
#pragma unroll
        for (int i = 0; i < 32; i += 8)
            Sb[(size_t)(d0 + threadIdx.y + i) * C_DIM + c0 + threadIdx.x] =
                tile[threadIdx.x][threadIdx.y + i];
    }
}

// ---------------- row norms: nrm[b][r] = A[b][r] . W[r] -----------------------
__global__ __launch_bounds__(256) void norm_dots() {
    int b = blockIdx.y;
    int row = blockIdx.x * 8 + (threadIdx.x >> 5);
    int lane = threadIdx.x & 31;
    const __nv_bfloat162* a =
        (const __nv_bfloat162*)(g_ab + ((size_t)b * 2 * C_DIM + row) * C_DIM);
    const __nv_bfloat162* wr = (const __nv_bfloat162*)(g_wb + (size_t)row * C_DIM);
    float s = 0.f;
#pragma unroll
    for (int i = lane; i < C_DIM / 2; i += 32) {
        __nv_bfloat162 av = a[i], wv2 = wr[i];
        s += __bfloat162float(av.x) * __bfloat162float(wv2.x)
           + __bfloat162float(av.y) * __bfloat162float(wv2.y);
    }
#pragma unroll
    for (int o = 16; o; o >>= 1) s += __shfl_xor_sync(0xffffffffu, s, o);
    if (lane == 0) g_nrm[(size_t)b * 2 * C_DIM + row] = s;
}

// ---------------- col ops: register-resident norm-scale + softmax -> bf16 M ---
// block (32 d, 16 c-strides); each thread owns 32 c-values in registers.
__global__ __launch_bounds__(512) void col_ops() {
    int b = blockIdx.y;
    int tx = threadIdx.x, ty = threadIdx.y;
    int d = blockIdx.x * 32 + tx;
    const size_t cc = (size_t)C_DIM * C_DIM;
    const float* Mo = g_m + (size_t)b * cc;
    __nv_bfloat16* Mb = g_mb + (size_t)b * cc;
    const float* nb = g_nrm + (size_t)b * 2 * C_DIM;

    __shared__ float inq_s[C_DIM];
    int li = ty * 32 + tx;
    inq_s[li] = rsqrtf(nb[li]);
    float ink = rsqrtf(nb[C_DIM + d]);
    __syncthreads();

    float mv[32];
    float mmax = -1e30f, mmin = 1e30f;
#pragma unroll
    for (int i = 0; i < 32; i++) {
        int c = ty + i * 16;
        float m = Mo[(size_t)c * C_DIM + d] * inq_s[c] * ink;
        mv[i] = m;
        mmax = fmaxf(mmax, m);
        mmin = fminf(mmin, m);
    }
    __shared__ float s1[16][33], s2[16][33];
    s1[ty][tx] = mmax; s2[ty][tx] = mmin;
    __syncthreads();
#pragma unroll
    for (int h = 8; h; h >>= 1) {
        if (ty < h) {
            s1[ty][tx] = fmaxf(s1[ty][tx], s1[ty + h][tx]);
            s2[ty][tx] = fminf(s2[ty][tx], s2[ty + h][tx]);
        }
        __syncthreads();
    }
    mmax = s1[0][tx]; mmin = s2[0][tx];
    __syncthreads();

    float inv = 4.0f / (1.0f - mmin + EPSV);
    float es = 0.f;
#pragma unroll
    for (int i = 0; i < 32; i++) {
        float e = __expf((mv[i] - mmax) * inv);
        mv[i] = e;
        es += e;
    }
    s1[ty][tx] = es;
    __syncthreads();
#pragma unroll
    for (int h = 8; h; h >>= 1) {
        if (ty < h) s1[ty][tx] += s1[ty + h][tx];
        __syncthreads();
    }
    float rs = 1.0f / s1[0][tx];
    float* rsum = g_rsum + (size_t)b * C_DIM;
#pragma unroll
    for (int i = 0; i < 32; i++) {
        int c = ty + i * 16;
        float v = mv[i] * rs;
        Mb[(size_t)c * C_DIM + d] = __float2bfloat16(v);
        float t = v;
#pragma unroll
        for (int off = 16; off; off >>= 1) t += __shfl_xor_sync(0xffffffffu, t, off);
        if (tx == 0) atomicAdd(&rsum[c], t);
    }
}

// ---------------- launch ------------------------------------------------------
extern "C" void kernel_launch(void* const* d_in, const int* in_sizes, int n_in,
                              void* d_out, int out_size) {
    const float* x  = (const float*)d_in[0];
    const float* wq = (const float*)d_in[1];
    const float* wk = (const float*)d_in[2];
    const float* wv = (const float*)d_in[3];
    const float* gamma = (const float*)d_in[4];
    float* out = (float*)d_out;

    void *p_xb, *p_wb, *p_spart, *p_sb, *p_ab, *p_rsum, *p_m, *p_mb, *p_mw;
    cudaGetSymbolAddress(&p_xb,  g_xb);
    cudaGetSymbolAddress(&p_wb,  g_wb);
    cudaGetSymbolAddress(&p_spart, g_spart);
    cudaGetSymbolAddress(&p_sb,  g_sb);
    cudaGetSymbolAddress(&p_ab,  g_ab);
    cudaGetSymbolAddress(&p_rsum, g_rsum);
    cudaGetSymbolAddress(&p_m,   g_m);
    cudaGetSymbolAddress(&p_mb,  g_mb);
    cudaGetSymbolAddress(&p_mw,  g_mw);

    cudaFuncSetAttribute((const void*)gemm_nt<0, 1>, cudaFuncAttributeMaxDynamicSharedMemorySize, 2 * STG_BYTES);
    cudaFuncSetAttribute(gemm_nt<0>, cudaFuncAttributeMaxDynamicSharedMemorySize, 2 * STG_BYTES);
    cudaFuncSetAttribute(gemm_nt<3>, cudaFuncAttributeMaxDynamicSharedMemorySize, 2 * STG_BYTES);
    cudaFuncSetAttribute(gemm_nt<5>, cudaFuncAttributeMaxDynamicSharedMemorySize, 2 * STG_BYTES);
    cudaFuncSetAttribute((const void*)gemm_nt<1, 0, 1>, cudaFuncAttributeMaxDynamicSharedMemorySize, 2 * STG_BYTES);

    const long long CN = (long long)C_DIM * N_DIM;
    const long long CC = (long long)C_DIM * C_DIM;

    // 1) x -> bf16 (streaming)
    cvt_x<<<4096, 256>>>(x);
    // 2) weights -> bf16 ([Wq;Wk] | Wv^T), zero rsum
    cvt_w<<<(C_DIM * C_DIM + 255) / 256, 256>>>(wq, wk, wv);
    // 3) S partials = x @ x^T (upper-tri tiles only), split-K=4
    gemm_nt<0, 1><<<dim3(C_DIM / BN, C_DIM / BM, BATCH * SKM), 256, 2 * STG_BYTES>>>(
        (const __nv_bfloat16*)p_xb, (const __nv_bfloat16*)p_xb, p_spart,
        C_DIM, N_DIM / SKM, N_DIM, N_DIM,
        CN, CN, CC, SKM, (long long)BATCH * CC, nullptr, nullptr);
    // 4) S = sum partials -> bf16, mirror
    sum_s_t<<<dim3(16, 16, BATCH), dim3(32, 8)>>>();
    // 5) [Aq;Ak] = [Wq;Wk] @ S : M=1024, N=512, K=512 -> bf16
    gemm_nt<3><<<dim3(C_DIM / BN, 1024 / BM, BATCH), 256, 2 * STG_BYTES>>>(
        (const __nv_bfloat16*)p_wb, (const __nv_bfloat16*)p_sb, p_ab,
        C_DIM, C_DIM, C_DIM, C_DIM,
        0LL, CC, 2 * CC, 1, 0LL, nullptr, nullptr);
    // 6) norms
    norm_dots<<<dim3(2 * C_DIM / 8, BATCH), 256>>>();
    // 7) G = Aq @ Wk^T -> fp32 g_m
    gemm_nt<0><<<dim3(C_DIM / BN, C_DIM / BM, BATCH), 256, 2 * STG_BYTES>>>(
        (const __nv_bfloat16*)p_ab, (const __nv_bfloat16*)p_wb + CC, p_m,
        C_DIM, C_DIM, C_DIM, C_DIM,
        2 * CC, 0LL, CC, 1, 0LL, nullptr, nullptr);
    // 8) col softmax (register-resident) -> bf16 M + row sums
    col_ops<<<dim3(C_DIM / 32, BATCH), dim3(32, 16)>>>();
    // 9) MW = (M/rowsum) @ Wv -> bf16 (EPI=5, rowsum via X)
    gemm_nt<5><<<dim3(C_DIM / BN, C_DIM / BM, BATCH), 256, 2 * STG_BYTES>>>(
        (const __nv_bfloat16*)p_mb, (const __nv_bfloat16*)p_wb + 2 * CC, p_mw,
        C_DIM, C_DIM, C_DIM, C_DIM,
        CC, 0LL, CC, 1, 0LL, (const float*)p_rsum, nullptr);
    // 10) out = x + gamma * (MW @ x) : NN B (x in [c][n] layout)
    gemm_nt<1, 0, 1><<<dim3(N_DIM / BN, C_DIM / BM, BATCH), 256, 2 * STG_BYTES>>>(
        (const __nv_bfloat16*)p_mw, (const __nv_bfloat16*)p_xb, out,
        N_DIM, C_DIM, C_DIM, N_DIM,
        CC, CN, CN, 1, 0LL, x, gamma);
}